// round 6
// baseline (speedup 1.0000x reference)
#include <cuda_runtime.h>
#include <cstdint>

#define B_DIM 1024
#define L_DIM 50
#define P_DIM 10
#define D_DIM 64
#define V_DIM 100000

#define BM 128
#define BN 128
#define KSX 72   // xs stride (floats): 72%32==8 -> clean 2-wf LDS.64
#define KSW 68   // ws stride (floats): 68%32==4 -> conflict-free LDS.32
#define NITER 8
#define NT_TOTAL ((V_DIM + BN - 1) / BN)       // 782
#define GX ((NT_TOTAL + NITER - 1) / NITER)    // 98

__device__ float g_x[B_DIM * D_DIM];
__device__ float g_b2p[V_DIM];   // b2 gathered through items

// ---------------------------------------------------------------------------
__global__ void prep_kernel(const int* __restrict__ item_seq,
                            const int* __restrict__ user_ids,
                            const float* __restrict__ item_emb,
                            const float* __restrict__ user_emb) {
    __shared__ int sidx[L_DIM];
    int b = blockIdx.x;
    int d = threadIdx.x;
    if (d < L_DIM) sidx[d] = item_seq[b * L_DIM + d];
    __syncthreads();

    float S = 0.f, Slast = 0.f;
#pragma unroll
    for (int j = 0; j < L_DIM; j++) {
        float v = item_emb[(size_t)sidx[j] * D_DIM + d];
        S += v;
        if (j >= L_DIM - P_DIM) Slast += v;
    }
    float high = S * (1.0f / L_DIM);
    float low  = Slast * (1.0f / P_DIM);
    float sm = high * S, tm = sm * S, fm = tm * S;
    float uni = low + high + (sm + tm + fm) * high;
    g_x[b * D_DIM + d] = user_emb[(size_t)user_ids[b] * D_DIM + d] + uni;
}

__global__ void bias_kernel(const float* __restrict__ b2,
                            const int* __restrict__ items) {
    int v = blockIdx.x * 256 + threadIdx.x;
    if (v < V_DIM) g_b2p[v] = b2[items[v]];
}

// ---------------------------------------------------------------------------
__device__ __forceinline__ void cp16(uint32_t dst, const float* src) {
    asm volatile("cp.async.cg.shared.global [%0], [%1], 16;" :: "r"(dst), "l"(src));
}
__device__ __forceinline__ void cp_commit() { asm volatile("cp.async.commit_group;" ::); }
__device__ __forceinline__ void cp_wait1()  { asm volatile("cp.async.wait_group 1;" ::: "memory"); }

// column permutation: acc col c (within 32-group) holds v-offset f(c)
__device__ __forceinline__ int colperm(int c) {
    // c = 8*na + 2*tg + b  ->  v = 8*tg + 2*na + b
    return 8 * ((c >> 1) & 3) + 2 * (c >> 3) + (c & 1);
}

// ---------------------------------------------------------------------------
// GEMM: out[b, v] = x[b,:] . W2[items[v],:] + b2p[v]
// ---------------------------------------------------------------------------
#define SM_XS   0
#define SM_W0   (BM * KSX * 4)                    // 36864
#define SM_W1   (SM_W0 + BN * KSW * 4)            // +34816
#define SM_B0   (SM_W1 + BN * KSW * 4)
#define SM_B1   (SM_B0 + BN * 4)
#define SM_TOTAL (SM_B1 + BN * 4)                 // 107520 B

__global__ void __launch_bounds__(256, 2)
gemm_kernel(const float* __restrict__ W2, const int* __restrict__ items,
            float* __restrict__ out) {
    extern __shared__ char smem[];
    float* xs = (float*)(smem + SM_XS);
    float* wbufs[2] = {(float*)(smem + SM_W0), (float*)(smem + SM_W1)};
    float* bbufs[2] = {(float*)(smem + SM_B0), (float*)(smem + SM_B1)};

    const int tid = threadIdx.x;
    const int m0 = blockIdx.y * BM;
    const int tile0 = blockIdx.x * NITER;

    // --- resident x tile, k-permuted: phys(8s + 2t + h) = logical(8s + t + 4h)
    {
        int row  = tid >> 1;
        int half = tid & 1;              // k range [32*half, 32*half+32)
        const float* src = &g_x[(size_t)(m0 + row) * D_DIM + 32 * half];
        float* dst = &xs[row * KSX];
#pragma unroll
        for (int j = 0; j < 8; j++) {
            float4 f = *(const float4*)(src + j * 4);
            int k0 = 32 * half + j * 4;
#pragma unroll
            for (int e = 0; e < 4; e++) {
                int k = k0 + e;
                int s = k >> 3, r3 = k & 7;
                int phys = 8 * s + 2 * (r3 & 3) + (r3 >> 2);
                dst[phys] = e == 0 ? f.x : e == 1 ? f.y : e == 2 ? f.z : f.w;
            }
        }
    }

    // gather row for prefetch: ws row r holds W2 for v = tile*128 + voff(r)
    const int prow = tid >> 1;
    const int pcol = (tid & 1) * 32;
    const int voff = (prow >> 5) * 32 + colperm(prow & 31);

    // --- prologue: prefetch tile0 -> buf0
    {
        int v = tile0 * BN + voff;
        int vc = v < V_DIM ? v : V_DIM - 1;
        const float* src = W2 + (size_t)items[vc] * D_DIM + pcol;
        uint32_t dst = (uint32_t)__cvta_generic_to_shared(&wbufs[0][prow * KSW + pcol]);
#pragma unroll
        for (int j = 0; j < 8; j++) cp16(dst + j * 16, src + j * 4);
        if (tid < 32) {
            int q = tile0 * BN + tid * 4;
            cp16((uint32_t)__cvta_generic_to_shared(&bbufs[0][tid * 4]),
                 &g_b2p[q < V_DIM ? q : V_DIM - 4]);
        }
        cp_commit();
    }

    const int warp = tid >> 5, lane = tid & 31;
    const int g = lane >> 2, tg = lane & 3;
    const int wm = (warp & 1) * 64;
    const int wn = (warp >> 1) * 32;

    for (int t = 0; t < NITER; t++) {
        int tile = tile0 + t;
        if (tile >= NT_TOTAL) tile = NT_TOTAL - 1;

        // --- prefetch t+1
        {
            int pt = tile0 + t + 1;
            if (pt >= NT_TOTAL) pt = NT_TOTAL - 1;
            float* wb = wbufs[(t + 1) & 1];
            int v = pt * BN + voff;
            int vc = v < V_DIM ? v : V_DIM - 1;
            const float* src = W2 + (size_t)items[vc] * D_DIM + pcol;
            uint32_t dst = (uint32_t)__cvta_generic_to_shared(&wb[prow * KSW + pcol]);
#pragma unroll
            for (int j = 0; j < 8; j++) cp16(dst + j * 16, src + j * 4);
            if (tid < 32) {
                int q = pt * BN + tid * 4;
                cp16((uint32_t)__cvta_generic_to_shared(&bbufs[(t + 1) & 1][tid * 4]),
                     &g_b2p[q < V_DIM ? q : V_DIM - 4]);
            }
            cp_commit();
        }

        cp_wait1();         // tile t landed (t+1 still in flight)
        __syncthreads();

        const uint32_t* wsu = (const uint32_t*)wbufs[t & 1];
        const float*    bs  = bbufs[t & 1];
        const int v0 = tile * BN;

        float acc[4][4][4];
#pragma unroll
        for (int ma = 0; ma < 4; ma++)
#pragma unroll
            for (int na = 0; na < 4; na++)
#pragma unroll
                for (int i = 0; i < 4; i++) acc[ma][na][i] = 0.f;

#pragma unroll
        for (int s = 0; s < 8; s++) {
            const int kp = s * 8 + 2 * tg;   // phys col of (k+tg, k+tg+4)
            uint2 alo[4], ahi[4];
#pragma unroll
            for (int ma = 0; ma < 4; ma++) {
                int rb = wm + ma * 16;
                alo[ma] = *(const uint2*)&xs[(rb + g) * KSX + kp];
                ahi[ma] = *(const uint2*)&xs[(rb + 8 + g) * KSX + kp];
            }
            const int k = s * 8;
            uint32_t bbf[4][2];
#pragma unroll
            for (int na = 0; na < 4; na++) {
                int cb = wn + na * 8 + g;
                bbf[na][0] = wsu[cb * KSW + k + tg];
                bbf[na][1] = wsu[cb * KSW + k + tg + 4];
            }
#pragma unroll
            for (int ma = 0; ma < 4; ma++)
#pragma unroll
                for (int na = 0; na < 4; na++) {
                    asm volatile(
                        "mma.sync.aligned.m16n8k8.row.col.f32.tf32.tf32.f32 "
                        "{%0,%1,%2,%3}, {%4,%5,%6,%7}, {%8,%9}, {%0,%1,%2,%3};"
                        : "+f"(acc[ma][na][0]), "+f"(acc[ma][na][1]),
                          "+f"(acc[ma][na][2]), "+f"(acc[ma][na][3])
                        : "r"(alo[ma].x), "r"(ahi[ma].x),
                          "r"(alo[ma].y), "r"(ahi[ma].y),
                          "r"(bbf[na][0]), "r"(bbf[na][1]));
                }
        }

        // --- epilogue: permuted cols -> per-lane 4 consecutive v -> STG.128
#pragma unroll
        for (int p = 0; p < 2; p++) {
            int q = wn + 8 * tg + 4 * p;          // v-offset of this lane's quad
            int v = v0 + q;
            if (v < V_DIM) {
                float4 bz = *(const float4*)&bs[q];
#pragma unroll
                for (int ma = 0; ma < 4; ma++) {
                    int r0 = m0 + wm + ma * 16 + g;
                    float4 o0 = make_float4(acc[ma][2 * p][0] + bz.x,
                                            acc[ma][2 * p][1] + bz.y,
                                            acc[ma][2 * p + 1][0] + bz.z,
                                            acc[ma][2 * p + 1][1] + bz.w);
                    float4 o1 = make_float4(acc[ma][2 * p][2] + bz.x,
                                            acc[ma][2 * p][3] + bz.y,
                                            acc[ma][2 * p + 1][2] + bz.z,
                                            acc[ma][2 * p + 1][3] + bz.w);
                    *(float4*)&out[(size_t)r0 * V_DIM + v] = o0;
                    *(float4*)&out[(size_t)(r0 + 8) * V_DIM + v] = o1;
                }
            }
        }
        __syncthreads();
    }
}

// ---------------------------------------------------------------------------
extern "C" void kernel_launch(void* const* d_in, const int* in_sizes, int n_in,
                              void* d_out, int out_size) {
    const int*   item_seq = (const int*)d_in[0];
    const int*   user_ids = (const int*)d_in[1];
    const int*   items    = (const int*)d_in[2];
    const float* item_emb = (const float*)d_in[3];
    const float* user_emb = (const float*)d_in[4];
    const float* W2       = (const float*)d_in[5];
    const float* b2       = (const float*)d_in[6];
    float* out = (float*)d_out;

    prep_kernel<<<B_DIM, D_DIM>>>(item_seq, user_ids, item_emb, user_emb);
    bias_kernel<<<(V_DIM + 255) / 256, 256>>>(b2, items);

    cudaFuncSetAttribute(gemm_kernel, cudaFuncAttributeMaxDynamicSharedMemorySize,
                         SM_TOTAL);
    dim3 grid(GX, B_DIM / BM);
    gemm_kernel<<<grid, 256, SM_TOTAL>>>(W2, items, out);
}

// round 7
// speedup vs baseline: 1.0042x; 1.0042x over previous
#include <cuda_runtime.h>
#include <cstdint>

#define B_DIM 1024
#define L_DIM 50
#define P_DIM 10
#define D_DIM 64
#define V_DIM 100000

#define BM 128
#define BN 128
#define KSX 72   // xs stride (floats): 72%32==8 -> clean 2-wf LDS.64
#define KSW 68   // ws stride (floats): 68%32==4 -> conflict-free LDS.32
#define NITER 8
#define NT_TOTAL ((V_DIM + BN - 1) / BN)       // 782
#define GX ((NT_TOTAL + NITER - 1) / NITER)    // 98

__device__ float g_x[B_DIM * D_DIM];
__device__ float g_b2p[V_DIM];   // b2 gathered through items

// ---------------------------------------------------------------------------
__global__ void prep_kernel(const int* __restrict__ item_seq,
                            const int* __restrict__ user_ids,
                            const float* __restrict__ item_emb,
                            const float* __restrict__ user_emb) {
    __shared__ int sidx[L_DIM];
    int b = blockIdx.x;
    int d = threadIdx.x;
    if (d < L_DIM) sidx[d] = item_seq[b * L_DIM + d];
    __syncthreads();

    float S = 0.f, Slast = 0.f;
#pragma unroll
    for (int j = 0; j < L_DIM; j++) {
        float v = item_emb[(size_t)sidx[j] * D_DIM + d];
        S += v;
        if (j >= L_DIM - P_DIM) Slast += v;
    }
    float high = S * (1.0f / L_DIM);
    float low  = Slast * (1.0f / P_DIM);
    float sm = high * S, tm = sm * S, fm = tm * S;
    float uni = low + high + (sm + tm + fm) * high;
    g_x[b * D_DIM + d] = user_emb[(size_t)user_ids[b] * D_DIM + d] + uni;
}

__global__ void bias_kernel(const float* __restrict__ b2,
                            const int* __restrict__ items) {
    int v = blockIdx.x * 256 + threadIdx.x;
    if (v < V_DIM) g_b2p[v] = b2[items[v]];
}

// ---------------------------------------------------------------------------
__device__ __forceinline__ void cp16(uint32_t dst, const float* src) {
    asm volatile("cp.async.cg.shared.global [%0], [%1], 16;" :: "r"(dst), "l"(src));
}
__device__ __forceinline__ void cp_commit() { asm volatile("cp.async.commit_group;" ::); }
__device__ __forceinline__ void cp_wait1()  { asm volatile("cp.async.wait_group 1;" ::: "memory"); }

// column permutation: acc col c (within 32-group) holds v-offset f(c)
__device__ __forceinline__ int colperm(int c) {
    // c = 8*na + 2*tg + b  ->  v = 8*tg + 2*na + b
    return 8 * ((c >> 1) & 3) + 2 * (c >> 3) + (c & 1);
}

// ---------------------------------------------------------------------------
// GEMM: out[b, v] = x[b,:] . W2[items[v],:] + b2p[v]
// ---------------------------------------------------------------------------
#define SM_XS   0
#define SM_W0   (BM * KSX * 4)                    // 36864
#define SM_W1   (SM_W0 + BN * KSW * 4)            // +34816
#define SM_B0   (SM_W1 + BN * KSW * 4)
#define SM_B1   (SM_B0 + BN * 4)
#define SM_TOTAL (SM_B1 + BN * 4)                 // 107520 B

__global__ void __launch_bounds__(256, 2)
gemm_kernel(const float* __restrict__ W2, const int* __restrict__ items,
            float* __restrict__ out) {
    extern __shared__ char smem[];
    float* xs = (float*)(smem + SM_XS);
    float* wbufs[2] = {(float*)(smem + SM_W0), (float*)(smem + SM_W1)};
    float* bbufs[2] = {(float*)(smem + SM_B0), (float*)(smem + SM_B1)};

    const int tid = threadIdx.x;
    const int m0 = blockIdx.y * BM;
    const int tile0 = blockIdx.x * NITER;

    // --- resident x tile, k-permuted: phys(8s + 2t + h) = logical(8s + t + 4h)
    {
        int row  = tid >> 1;
        int half = tid & 1;              // k range [32*half, 32*half+32)
        const float* src = &g_x[(size_t)(m0 + row) * D_DIM + 32 * half];
        float* dst = &xs[row * KSX];
#pragma unroll
        for (int j = 0; j < 8; j++) {
            float4 f = *(const float4*)(src + j * 4);
            int k0 = 32 * half + j * 4;
#pragma unroll
            for (int e = 0; e < 4; e++) {
                int k = k0 + e;
                int s = k >> 3, r3 = k & 7;
                int phys = 8 * s + 2 * (r3 & 3) + (r3 >> 2);
                dst[phys] = e == 0 ? f.x : e == 1 ? f.y : e == 2 ? f.z : f.w;
            }
        }
    }

    // gather row for prefetch: ws row r holds W2 for v = tile*128 + voff(r)
    const int prow = tid >> 1;
    const int pcol = (tid & 1) * 32;
    const int voff = (prow >> 5) * 32 + colperm(prow & 31);

    // --- prologue: prefetch tile0 -> buf0
    {
        int v = tile0 * BN + voff;
        int vc = v < V_DIM ? v : V_DIM - 1;
        const float* src = W2 + (size_t)items[vc] * D_DIM + pcol;
        uint32_t dst = (uint32_t)__cvta_generic_to_shared(&wbufs[0][prow * KSW + pcol]);
#pragma unroll
        for (int j = 0; j < 8; j++) cp16(dst + j * 16, src + j * 4);
        if (tid < 32) {
            int q = tile0 * BN + tid * 4;
            cp16((uint32_t)__cvta_generic_to_shared(&bbufs[0][tid * 4]),
                 &g_b2p[q < V_DIM ? q : V_DIM - 4]);
        }
        cp_commit();
    }

    const int warp = tid >> 5, lane = tid & 31;
    const int g = lane >> 2, tg = lane & 3;
    const int wm = (warp & 1) * 64;
    const int wn = (warp >> 1) * 32;

    for (int t = 0; t < NITER; t++) {
        int tile = tile0 + t;
        if (tile >= NT_TOTAL) tile = NT_TOTAL - 1;

        // --- prefetch t+1
        {
            int pt = tile0 + t + 1;
            if (pt >= NT_TOTAL) pt = NT_TOTAL - 1;
            float* wb = wbufs[(t + 1) & 1];
            int v = pt * BN + voff;
            int vc = v < V_DIM ? v : V_DIM - 1;
            const float* src = W2 + (size_t)items[vc] * D_DIM + pcol;
            uint32_t dst = (uint32_t)__cvta_generic_to_shared(&wb[prow * KSW + pcol]);
#pragma unroll
            for (int j = 0; j < 8; j++) cp16(dst + j * 16, src + j * 4);
            if (tid < 32) {
                int q = pt * BN + tid * 4;
                cp16((uint32_t)__cvta_generic_to_shared(&bbufs[(t + 1) & 1][tid * 4]),
                     &g_b2p[q < V_DIM ? q : V_DIM - 4]);
            }
            cp_commit();
        }

        cp_wait1();         // tile t landed (t+1 still in flight)
        __syncthreads();

        const uint32_t* wsu = (const uint32_t*)wbufs[t & 1];
        const float*    bs  = bbufs[t & 1];
        const int v0 = tile * BN;

        float acc[4][4][4];
#pragma unroll
        for (int ma = 0; ma < 4; ma++)
#pragma unroll
            for (int na = 0; na < 4; na++)
#pragma unroll
                for (int i = 0; i < 4; i++) acc[ma][na][i] = 0.f;

#pragma unroll
        for (int s = 0; s < 8; s++) {
            const int kp = s * 8 + 2 * tg;   // phys col of (k+tg, k+tg+4)
            uint2 alo[4], ahi[4];
#pragma unroll
            for (int ma = 0; ma < 4; ma++) {
                int rb = wm + ma * 16;
                alo[ma] = *(const uint2*)&xs[(rb + g) * KSX + kp];
                ahi[ma] = *(const uint2*)&xs[(rb + 8 + g) * KSX + kp];
            }
            const int k = s * 8;
            uint32_t bbf[4][2];
#pragma unroll
            for (int na = 0; na < 4; na++) {
                int cb = wn + na * 8 + g;
                bbf[na][0] = wsu[cb * KSW + k + tg];
                bbf[na][1] = wsu[cb * KSW + k + tg + 4];
            }
#pragma unroll
            for (int ma = 0; ma < 4; ma++)
#pragma unroll
                for (int na = 0; na < 4; na++) {
                    asm volatile(
                        "mma.sync.aligned.m16n8k8.row.col.f32.tf32.tf32.f32 "
                        "{%0,%1,%2,%3}, {%4,%5,%6,%7}, {%8,%9}, {%0,%1,%2,%3};"
                        : "+f"(acc[ma][na][0]), "+f"(acc[ma][na][1]),
                          "+f"(acc[ma][na][2]), "+f"(acc[ma][na][3])
                        : "r"(alo[ma].x), "r"(ahi[ma].x),
                          "r"(alo[ma].y), "r"(ahi[ma].y),
                          "r"(bbf[na][0]), "r"(bbf[na][1]));
                }
        }

        // --- epilogue: permuted cols -> per-lane 4 consecutive v -> STG.128
#pragma unroll
        for (int p = 0; p < 2; p++) {
            int q = wn + 8 * tg + 4 * p;          // v-offset of this lane's quad
            int v = v0 + q;
            if (v < V_DIM) {
                float4 bz = *(const float4*)&bs[q];
#pragma unroll
                for (int ma = 0; ma < 4; ma++) {
                    int r0 = m0 + wm + ma * 16 + g;
                    float4 o0 = make_float4(acc[ma][2 * p][0] + bz.x,
                                            acc[ma][2 * p][1] + bz.y,
                                            acc[ma][2 * p + 1][0] + bz.z,
                                            acc[ma][2 * p + 1][1] + bz.w);
                    float4 o1 = make_float4(acc[ma][2 * p][2] + bz.x,
                                            acc[ma][2 * p][3] + bz.y,
                                            acc[ma][2 * p + 1][2] + bz.z,
                                            acc[ma][2 * p + 1][3] + bz.w);
                    *(float4*)&out[(size_t)r0 * V_DIM + v] = o0;
                    *(float4*)&out[(size_t)(r0 + 8) * V_DIM + v] = o1;
                }
            }
        }
        __syncthreads();
    }
}

// ---------------------------------------------------------------------------
extern "C" void kernel_launch(void* const* d_in, const int* in_sizes, int n_in,
                              void* d_out, int out_size) {
    const int*   item_seq = (const int*)d_in[0];
    const int*   user_ids = (const int*)d_in[1];
    const int*   items    = (const int*)d_in[2];
    const float* item_emb = (const float*)d_in[3];
    const float* user_emb = (const float*)d_in[4];
    const float* W2       = (const float*)d_in[5];
    const float* b2       = (const float*)d_in[6];
    float* out = (float*)d_out;

    prep_kernel<<<B_DIM, D_DIM>>>(item_seq, user_ids, item_emb, user_emb);
    bias_kernel<<<(V_DIM + 255) / 256, 256>>>(b2, items);

    cudaFuncSetAttribute(gemm_kernel, cudaFuncAttributeMaxDynamicSharedMemorySize,
                         SM_TOTAL);
    dim3 grid(GX, B_DIM / BM);
    gemm_kernel<<<grid, 256, SM_TOTAL>>>(W2, items, out);
}

// round 8
// speedup vs baseline: 1.0087x; 1.0045x over previous
#include <cuda_runtime.h>
#include <cstdint>

#define B_DIM 1024
#define L_DIM 50
#define P_DIM 10
#define D_DIM 64
#define V_DIM 100000

#define BM 128
#define BN 128
#define KSX 72   // xs stride (floats): 72%32==8 -> clean 2-wf LDS.64
#define KSW 68   // ws stride (floats): 68%32==4 -> conflict-free LDS.32
#define NITER 8
#define NT_TOTAL ((V_DIM + BN - 1) / BN)       // 782
#define GX ((NT_TOTAL + NITER - 1) / NITER)    // 98

__device__ float g_x[B_DIM * D_DIM];
__device__ float g_b2p[V_DIM];   // b2 gathered through items

// ---------------------------------------------------------------------------
__global__ void prep_kernel(const int* __restrict__ item_seq,
                            const int* __restrict__ user_ids,
                            const float* __restrict__ item_emb,
                            const float* __restrict__ user_emb) {
    __shared__ int sidx[L_DIM];
    int b = blockIdx.x;
    int d = threadIdx.x;
    if (d < L_DIM) sidx[d] = item_seq[b * L_DIM + d];
    __syncthreads();

    float S = 0.f, Slast = 0.f;
#pragma unroll
    for (int j = 0; j < L_DIM; j++) {
        float v = item_emb[(size_t)sidx[j] * D_DIM + d];
        S += v;
        if (j >= L_DIM - P_DIM) Slast += v;
    }
    float high = S * (1.0f / L_DIM);
    float low  = Slast * (1.0f / P_DIM);
    float sm = high * S, tm = sm * S, fm = tm * S;
    float uni = low + high + (sm + tm + fm) * high;
    g_x[b * D_DIM + d] = user_emb[(size_t)user_ids[b] * D_DIM + d] + uni;
}

__global__ void bias_kernel(const float* __restrict__ b2,
                            const int* __restrict__ items) {
    int v = blockIdx.x * 256 + threadIdx.x;
    if (v < V_DIM) g_b2p[v] = b2[items[v]];
}

// ---------------------------------------------------------------------------
__device__ __forceinline__ void cp16(uint32_t dst, const float* src) {
    asm volatile("cp.async.cg.shared.global [%0], [%1], 16;" :: "r"(dst), "l"(src));
}
__device__ __forceinline__ void cp_commit() { asm volatile("cp.async.commit_group;" ::); }
__device__ __forceinline__ void cp_wait1()  { asm volatile("cp.async.wait_group 1;" ::: "memory"); }

// column permutation: acc col c (within 32-group) holds v-offset f(c)
__device__ __forceinline__ int colperm(int c) {
    // c = 8*na + 2*tg + b  ->  v = 8*tg + 2*na + b
    return 8 * ((c >> 1) & 3) + 2 * (c >> 3) + (c & 1);
}

// ---------------------------------------------------------------------------
// GEMM: out[b, v] = x[b,:] . W2[items[v],:] + b2p[v]
// ---------------------------------------------------------------------------
#define SM_XS   0
#define SM_W0   (BM * KSX * 4)                    // 36864
#define SM_W1   (SM_W0 + BN * KSW * 4)            // +34816
#define SM_B0   (SM_W1 + BN * KSW * 4)
#define SM_B1   (SM_B0 + BN * 4)
#define SM_TOTAL (SM_B1 + BN * 4)                 // 107520 B

__global__ void __launch_bounds__(256, 2)
gemm_kernel(const float* __restrict__ W2, const int* __restrict__ items,
            float* __restrict__ out) {
    extern __shared__ char smem[];
    float* xs = (float*)(smem + SM_XS);
    float* wbufs[2] = {(float*)(smem + SM_W0), (float*)(smem + SM_W1)};
    float* bbufs[2] = {(float*)(smem + SM_B0), (float*)(smem + SM_B1)};

    const int tid = threadIdx.x;
    const int m0 = blockIdx.y * BM;
    const int tile0 = blockIdx.x * NITER;

    // --- resident x tile, k-permuted: phys(8s + 2t + h) = logical(8s + t + 4h)
    {
        int row  = tid >> 1;
        int half = tid & 1;              // k range [32*half, 32*half+32)
        const float* src = &g_x[(size_t)(m0 + row) * D_DIM + 32 * half];
        float* dst = &xs[row * KSX];
#pragma unroll
        for (int j = 0; j < 8; j++) {
            float4 f = *(const float4*)(src + j * 4);
            int k0 = 32 * half + j * 4;
#pragma unroll
            for (int e = 0; e < 4; e++) {
                int k = k0 + e;
                int s = k >> 3, r3 = k & 7;
                int phys = 8 * s + 2 * (r3 & 3) + (r3 >> 2);
                dst[phys] = e == 0 ? f.x : e == 1 ? f.y : e == 2 ? f.z : f.w;
            }
        }
    }

    // gather row for prefetch: ws row r holds W2 for v = tile*128 + voff(r)
    const int prow = tid >> 1;
    const int pcol = (tid & 1) * 32;
    const int voff = (prow >> 5) * 32 + colperm(prow & 31);

    // --- prologue: prefetch tile0 -> buf0
    {
        int v = tile0 * BN + voff;
        int vc = v < V_DIM ? v : V_DIM - 1;
        const float* src = W2 + (size_t)items[vc] * D_DIM + pcol;
        uint32_t dst = (uint32_t)__cvta_generic_to_shared(&wbufs[0][prow * KSW + pcol]);
#pragma unroll
        for (int j = 0; j < 8; j++) cp16(dst + j * 16, src + j * 4);
        if (tid < 32) {
            int q = tile0 * BN + tid * 4;
            cp16((uint32_t)__cvta_generic_to_shared(&bbufs[0][tid * 4]),
                 &g_b2p[q < V_DIM ? q : V_DIM - 4]);
        }
        cp_commit();
    }

    const int warp = tid >> 5, lane = tid & 31;
    const int g = lane >> 2, tg = lane & 3;
    const int wm = (warp & 1) * 64;
    const int wn = (warp >> 1) * 32;

    for (int t = 0; t < NITER; t++) {
        int tile = tile0 + t;
        if (tile >= NT_TOTAL) tile = NT_TOTAL - 1;

        // --- prefetch t+1
        {
            int pt = tile0 + t + 1;
            if (pt >= NT_TOTAL) pt = NT_TOTAL - 1;
            float* wb = wbufs[(t + 1) & 1];
            int v = pt * BN + voff;
            int vc = v < V_DIM ? v : V_DIM - 1;
            const float* src = W2 + (size_t)items[vc] * D_DIM + pcol;
            uint32_t dst = (uint32_t)__cvta_generic_to_shared(&wb[prow * KSW + pcol]);
#pragma unroll
            for (int j = 0; j < 8; j++) cp16(dst + j * 16, src + j * 4);
            if (tid < 32) {
                int q = pt * BN + tid * 4;
                cp16((uint32_t)__cvta_generic_to_shared(&bbufs[(t + 1) & 1][tid * 4]),
                     &g_b2p[q < V_DIM ? q : V_DIM - 4]);
            }
            cp_commit();
        }

        cp_wait1();         // tile t landed (t+1 still in flight)
        __syncthreads();

        const uint32_t* wsu = (const uint32_t*)wbufs[t & 1];
        const float*    bs  = bbufs[t & 1];
        const int v0 = tile * BN;

        float acc[4][4][4];
#pragma unroll
        for (int ma = 0; ma < 4; ma++)
#pragma unroll
            for (int na = 0; na < 4; na++)
#pragma unroll
                for (int i = 0; i < 4; i++) acc[ma][na][i] = 0.f;

#pragma unroll
        for (int s = 0; s < 8; s++) {
            const int kp = s * 8 + 2 * tg;   // phys col of (k+tg, k+tg+4)
            uint2 alo[4], ahi[4];
#pragma unroll
            for (int ma = 0; ma < 4; ma++) {
                int rb = wm + ma * 16;
                alo[ma] = *(const uint2*)&xs[(rb + g) * KSX + kp];
                ahi[ma] = *(const uint2*)&xs[(rb + 8 + g) * KSX + kp];
            }
            const int k = s * 8;
            uint32_t bbf[4][2];
#pragma unroll
            for (int na = 0; na < 4; na++) {
                int cb = wn + na * 8 + g;
                bbf[na][0] = wsu[cb * KSW + k + tg];
                bbf[na][1] = wsu[cb * KSW + k + tg + 4];
            }
#pragma unroll
            for (int ma = 0; ma < 4; ma++)
#pragma unroll
                for (int na = 0; na < 4; na++) {
                    asm volatile(
                        "mma.sync.aligned.m16n8k8.row.col.f32.tf32.tf32.f32 "
                        "{%0,%1,%2,%3}, {%4,%5,%6,%7}, {%8,%9}, {%0,%1,%2,%3};"
                        : "+f"(acc[ma][na][0]), "+f"(acc[ma][na][1]),
                          "+f"(acc[ma][na][2]), "+f"(acc[ma][na][3])
                        : "r"(alo[ma].x), "r"(ahi[ma].x),
                          "r"(alo[ma].y), "r"(ahi[ma].y),
                          "r"(bbf[na][0]), "r"(bbf[na][1]));
                }
        }

        // --- epilogue: permuted cols -> per-lane 4 consecutive v -> STG.128
#pragma unroll
        for (int p = 0; p < 2; p++) {
            int q = wn + 8 * tg + 4 * p;          // v-offset of this lane's quad
            int v = v0 + q;
            if (v < V_DIM) {
                float4 bz = *(const float4*)&bs[q];
#pragma unroll
                for (int ma = 0; ma < 4; ma++) {
                    int r0 = m0 + wm + ma * 16 + g;
                    float4 o0 = make_float4(acc[ma][2 * p][0] + bz.x,
                                            acc[ma][2 * p][1] + bz.y,
                                            acc[ma][2 * p + 1][0] + bz.z,
                                            acc[ma][2 * p + 1][1] + bz.w);
                    float4 o1 = make_float4(acc[ma][2 * p][2] + bz.x,
                                            acc[ma][2 * p][3] + bz.y,
                                            acc[ma][2 * p + 1][2] + bz.z,
                                            acc[ma][2 * p + 1][3] + bz.w);
                    *(float4*)&out[(size_t)r0 * V_DIM + v] = o0;
                    *(float4*)&out[(size_t)(r0 + 8) * V_DIM + v] = o1;
                }
            }
        }
        __syncthreads();
    }
}

// ---------------------------------------------------------------------------
extern "C" void kernel_launch(void* const* d_in, const int* in_sizes, int n_in,
                              void* d_out, int out_size) {
    const int*   item_seq = (const int*)d_in[0];
    const int*   user_ids = (const int*)d_in[1];
    const int*   items    = (const int*)d_in[2];
    const float* item_emb = (const float*)d_in[3];
    const float* user_emb = (const float*)d_in[4];
    const float* W2       = (const float*)d_in[5];
    const float* b2       = (const float*)d_in[6];
    float* out = (float*)d_out;

    prep_kernel<<<B_DIM, D_DIM>>>(item_seq, user_ids, item_emb, user_emb);
    bias_kernel<<<(V_DIM + 255) / 256, 256>>>(b2, items);

    cudaFuncSetAttribute(gemm_kernel, cudaFuncAttributeMaxDynamicSharedMemorySize,
                         SM_TOTAL);
    dim3 grid(GX, B_DIM / BM);
    gemm_kernel<<<grid, 256, SM_TOTAL>>>(W2, items, out);
}